// round 1
// baseline (speedup 1.0000x reference)
#include <cuda_runtime.h>

// Fused: logits = embs @ [W_status; W_flight]^T + b ; two softmaxes; combine
// into 63 outputs per token:
//   out[0] = s0 (no_flight), out[1] = s2 (cancel), out[2] = s1 (no_reservation),
//   out[3+j]  = s4 * f[j]  (book  * flight_probs)
//   out[33+j] = s3 * f[j]  (change* flight_probs)
//
// One warp per token. Lanes split the 1024-dim embedding (32 floats/lane,
// loaded as 8x float4, coalesced). 35 per-lane partial dots accumulated in
// registers; weights read via LDG (143KB total -> L1-resident, broadcast
// across warps). Butterfly warp reduction, redundant per-lane softmax,
// predicated unrolled stores.

#define EMB_DIM 1024
#define NS 5
#define NF 30
#define NOUT 35
#define OUTC 63

__global__ __launch_bounds__(256) void aux2_fused_kernel(
    const float* __restrict__ embs,
    const float* __restrict__ W_status,
    const float* __restrict__ b_status,
    const float* __restrict__ W_flight,
    const float* __restrict__ b_flight,
    float* __restrict__ out,
    int ntok)
{
    const int warp = threadIdx.x >> 5;
    const int lane = threadIdx.x & 31;
    const int token = blockIdx.x * 8 + warp;
    if (token >= ntok) return;

    // Load this token's embedding slice into registers: 8 x float4 per lane.
    const float4* e4 = reinterpret_cast<const float4*>(embs + (size_t)token * EMB_DIM);
    float4 e[8];
#pragma unroll
    for (int i = 0; i < 8; i++) e[i] = e4[lane + 32 * i];

    float acc[NOUT];
#pragma unroll
    for (int o = 0; o < NOUT; o++) acc[o] = 0.0f;

    // Status logits (5 rows)
#pragma unroll
    for (int o = 0; o < NS; o++) {
        const float4* w4 = reinterpret_cast<const float4*>(W_status + o * EMB_DIM);
        float a = 0.0f;
#pragma unroll
        for (int i = 0; i < 8; i++) {
            float4 w = w4[lane + 32 * i];
            a += e[i].x * w.x;
            a += e[i].y * w.y;
            a += e[i].z * w.z;
            a += e[i].w * w.w;
        }
        acc[o] = a;
    }

    // Flight logits (30 rows)
#pragma unroll
    for (int o = 0; o < NF; o++) {
        const float4* w4 = reinterpret_cast<const float4*>(W_flight + o * EMB_DIM);
        float a = 0.0f;
#pragma unroll
        for (int i = 0; i < 8; i++) {
            float4 w = w4[lane + 32 * i];
            a += e[i].x * w.x;
            a += e[i].y * w.y;
            a += e[i].z * w.z;
            a += e[i].w * w.w;
        }
        acc[NS + o] = a;
    }

    // Warp butterfly reduction: after this every lane holds all 35 full dots.
#pragma unroll
    for (int o = 0; o < NOUT; o++) {
        float v = acc[o];
        v += __shfl_xor_sync(0xFFFFFFFFu, v, 16);
        v += __shfl_xor_sync(0xFFFFFFFFu, v, 8);
        v += __shfl_xor_sync(0xFFFFFFFFu, v, 4);
        v += __shfl_xor_sync(0xFFFFFFFFu, v, 2);
        v += __shfl_xor_sync(0xFFFFFFFFu, v, 1);
        acc[o] = v;
    }

    // Add biases (broadcast LDG; tiny, L1/const-cached)
    float sl[NS];
#pragma unroll
    for (int o = 0; o < NS; o++) sl[o] = acc[o] + b_status[o];
    float fl[NF];
#pragma unroll
    for (int o = 0; o < NF; o++) fl[o] = acc[NS + o] + b_flight[o];

    // Status softmax (5)
    float smax = sl[0];
#pragma unroll
    for (int o = 1; o < NS; o++) smax = fmaxf(smax, sl[o]);
    float ssum = 0.0f;
#pragma unroll
    for (int o = 0; o < NS; o++) { sl[o] = __expf(sl[o] - smax); ssum += sl[o]; }
    float sinv = 1.0f / ssum;
#pragma unroll
    for (int o = 0; o < NS; o++) sl[o] *= sinv;

    // Flight softmax (30)
    float fmaxv = fl[0];
#pragma unroll
    for (int o = 1; o < NF; o++) fmaxv = fmaxf(fmaxv, fl[o]);
    float fsum = 0.0f;
#pragma unroll
    for (int o = 0; o < NF; o++) { fl[o] = __expf(fl[o] - fmaxv); fsum += fl[o]; }
    float finv = 1.0f / fsum;
#pragma unroll
    for (int o = 0; o < NF; o++) fl[o] *= finv;

    const float book = sl[4];
    const float change = sl[3];

    float* op = out + (size_t)token * OUTC;

    // Predicated unrolled stores: static indexing into register arrays,
    // one active lane per element (lane = j & 31).
#pragma unroll
    for (int j = 0; j < OUTC; j++) {
        float v;
        if (j == 0)       v = sl[0];
        else if (j == 1)  v = sl[2];
        else if (j == 2)  v = sl[1];
        else if (j < 33)  v = book * fl[j - 3];
        else              v = change * fl[j - 33];
        if (lane == (j & 31)) op[j] = v;
    }
}

extern "C" void kernel_launch(void* const* d_in, const int* in_sizes, int n_in,
                              void* d_out, int out_size) {
    const float* embs     = (const float*)d_in[0];
    const float* W_status = (const float*)d_in[1];
    const float* b_status = (const float*)d_in[2];
    const float* W_flight = (const float*)d_in[3];
    const float* b_flight = (const float*)d_in[4];
    float* out = (float*)d_out;

    int ntok = in_sizes[0] / EMB_DIM;  // B*T = 65536
    int blocks = (ntok + 7) / 8;       // 8 warps (tokens) per block
    aux2_fused_kernel<<<blocks, 256>>>(embs, W_status, b_status,
                                       W_flight, b_flight, out, ntok);
}

// round 2
// speedup vs baseline: 2.4879x; 2.4879x over previous
#include <cuda_runtime.h>

// Skinny GEMM + fused dual softmax.
// C[65536, 35] = embs[65536,1024] @ W^T ; W = [W_status(5); W_flight(30)]
// CTA: BM=128 tokens x BN=40 (35 padded) outputs, BK=32 K-chunk,
// cp.async double-buffered smem staging, f32x2 packed FMA (2 MACs/instr),
// thread tile 8 tokens x 5 outputs. Epilogue: per-token softmax fused.

#define EMB   1024
#define NS    5
#define NF    30
#define NL    35      // total logits
#define OUTC  63
#define BM    128
#define BK    32
#define STR   34      // smem row stride (floats): +2 pad -> conflict-free LDS.64
#define LSTR  41      // logit smem stride
#define NTH   128
#define NCHUNK (EMB / BK)   // 32

typedef unsigned long long ull;

__device__ __forceinline__ void fma2(ull& d, ull a, ull b) {
    asm volatile("fma.rn.f32x2 %0, %1, %2, %0;" : "+l"(d) : "l"(a), "l"(b));
}
__device__ __forceinline__ float2 unpack2(ull v) {
    float2 r;
    asm("mov.b64 {%0, %1}, %2;" : "=f"(r.x), "=f"(r.y) : "l"(v));
    return r;
}
__device__ __forceinline__ void cp8(float* dst, const float* src) {
    unsigned s = (unsigned)__cvta_generic_to_shared(dst);
    asm volatile("cp.async.ca.shared.global [%0], [%1], 8;" :: "r"(s), "l"(src));
}
__device__ __forceinline__ void cp_commit() {
    asm volatile("cp.async.commit_group;");
}
template<int N> __device__ __forceinline__ void cp_wait() {
    asm volatile("cp.async.wait_group %0;" :: "n"(N));
}

__global__ __launch_bounds__(NTH, 2) void aux2_gemm_kernel(
    const float* __restrict__ embs,
    const float* __restrict__ W_status,
    const float* __restrict__ b_status,
    const float* __restrict__ W_flight,
    const float* __restrict__ b_flight,
    float* __restrict__ out,
    int ntok)
{
    __shared__ float sA[2][BM * STR];   // 2 x 17.4 KB
    __shared__ float sB[2][40 * STR];   // 2 x 5.4 KB (rows 35..39 garbage, unused)

    const int tid = threadIdx.x;
    const int tg  = tid & 15;           // token group 0..15
    const int ng  = tid >> 4;           // output group 0..7 (n = ng*5+j)
    const long tok0 = (long)blockIdx.x * BM;
    const float* Ablk = embs + tok0 * EMB;

    // ---- async copy helpers ----
    auto copyA = [&](float* dA, int kc) {
#pragma unroll
        for (int it = 0; it < 16; ++it) {
            int idx = it * NTH + tid;           // 0..2047  (128 rows x 16 pairs)
            int row = idx >> 4, pr = idx & 15;
            cp8(dA + row * STR + pr * 2, Ablk + (long)row * EMB + kc + pr * 2);
        }
    };
    auto copyB = [&](float* dB, int kc) {
#pragma unroll
        for (int it = 0; it < 5; ++it) {
            int idx = it * NTH + tid;           // 0..639, need 560 (35 rows x 16 pairs)
            if (idx < 560) {
                int row = idx >> 4, pr = idx & 15;
                const float* src = (row < NS) ? (W_status + row * EMB)
                                              : (W_flight + (row - NS) * EMB);
                cp8(dB + row * STR + pr * 2, src + kc + pr * 2);
            }
        }
    };

    ull acc[8][5];
#pragma unroll
    for (int i = 0; i < 8; ++i)
#pragma unroll
        for (int j = 0; j < 5; ++j) acc[i][j] = 0ull;  // {0.f, 0.f}

    // ---- prologue ----
    copyA(sA[0], 0);
    copyB(sB[0], 0);
    cp_commit();

    // ---- main loop: double-buffered ----
    for (int c = 0; c < NCHUNK; ++c) {
        if (c < NCHUNK - 1) {
            copyA(sA[(c + 1) & 1], (c + 1) * BK);
            copyB(sB[(c + 1) & 1], (c + 1) * BK);
            cp_commit();
            cp_wait<1>();      // chunk c's data has landed
        } else {
            cp_wait<0>();
        }
        __syncthreads();

        const float* A = sA[c & 1];
        const float* B = sB[c & 1];
#pragma unroll
        for (int kp = 0; kp < BK / 2; ++kp) {
            ull b2[5], a2[8];
#pragma unroll
            for (int j = 0; j < 5; ++j)
                b2[j] = *(const ull*)(B + (ng * 5 + j) * STR + 2 * kp);
#pragma unroll
            for (int i = 0; i < 8; ++i)
                a2[i] = *(const ull*)(A + (tg + 16 * i) * STR + 2 * kp);
#pragma unroll
            for (int i = 0; i < 8; ++i)
#pragma unroll
                for (int j = 0; j < 5; ++j)
                    fma2(acc[i][j], a2[i], b2[j]);
        }
        __syncthreads();   // protect buf before it is refilled
    }

    // ---- epilogue: logits -> smem (reuse sA), then per-token softmax ----
    float* Ls = (float*)sA;   // 128 x LSTR floats = 21 KB <= sA
#pragma unroll
    for (int i = 0; i < 8; ++i) {
        int t = tg + 16 * i;
#pragma unroll
        for (int j = 0; j < 5; ++j) {
            int n = ng * 5 + j;
            if (n < NL) {
                float2 v = unpack2(acc[i][j]);
                Ls[t * LSTR + n] = v.x + v.y;
            }
        }
    }
    __syncthreads();

    // one thread per token
    {
        const int t = tid;
        float sl[NS], fl[NF];
#pragma unroll
        for (int n = 0; n < NS; ++n) sl[n] = Ls[t * LSTR + n] + b_status[n];
#pragma unroll
        for (int n = 0; n < NF; ++n) fl[n] = Ls[t * LSTR + NS + n] + b_flight[n];

        float smax = sl[0];
#pragma unroll
        for (int n = 1; n < NS; ++n) smax = fmaxf(smax, sl[n]);
        float ssum = 0.f;
#pragma unroll
        for (int n = 0; n < NS; ++n) { sl[n] = __expf(sl[n] - smax); ssum += sl[n]; }
        float sinv = 1.f / ssum;
#pragma unroll
        for (int n = 0; n < NS; ++n) sl[n] *= sinv;

        float fm = fl[0];
#pragma unroll
        for (int n = 1; n < NF; ++n) fm = fmaxf(fm, fl[n]);
        float fsum = 0.f;
#pragma unroll
        for (int n = 0; n < NF; ++n) { fl[n] = __expf(fl[n] - fm); fsum += fl[n]; }
        float finv = 1.f / fsum;
#pragma unroll
        for (int n = 0; n < NF; ++n) fl[n] *= finv;

        const float book = sl[4], change = sl[3];
        long token = tok0 + t;
        if (token < ntok) {
            float* op = out + token * (long)OUTC;
            op[0] = sl[0];
            op[1] = sl[2];
            op[2] = sl[1];
#pragma unroll
            for (int j = 0; j < NF; ++j) {
                op[3 + j]  = book   * fl[j];
                op[33 + j] = change * fl[j];
            }
        }
    }
}

extern "C" void kernel_launch(void* const* d_in, const int* in_sizes, int n_in,
                              void* d_out, int out_size) {
    const float* embs     = (const float*)d_in[0];
    const float* W_status = (const float*)d_in[1];
    const float* b_status = (const float*)d_in[2];
    const float* W_flight = (const float*)d_in[3];
    const float* b_flight = (const float*)d_in[4];
    float* out = (float*)d_out;

    int ntok = in_sizes[0] / EMB;     // 65536
    int blocks = ntok / BM;           // 512
    aux2_gemm_kernel<<<blocks, NTH>>>(embs, W_status, b_status,
                                      W_flight, b_flight, out, ntok);
}

// round 4
// speedup vs baseline: 4.3787x; 1.7600x over previous
#include <cuda_runtime.h>
#include <cstdint>

// Skinny GEMM via mma.sync tf32 (portable PTX, tensor pipe) + fused dual softmax.
// C[65536,40] = embs[65536,1024] @ W^T, W = [W_status(5); W_flight(30); zeros(5)]
// BM=128 tokens x 40 logits per CTA, BK=32 K-chunk, cp.async double-buffered.
// Warp w owns tokens [32w, 32w+32): 2 m16 tiles x 5 n8 tiles, K=8 per MMA.

#define EMB    1024
#define NS     5
#define NF     30
#define NL     35
#define OUTC   63
#define BM     128
#define BK     32
#define ASTR   36     // smem strides (floats): bank=(4*row+col)&31 -> conflict-free frags
#define BSTR   36
#define LSTR   41
#define NTH    128
#define NCHUNK 32

__device__ __forceinline__ void cp16(float* dst, const float* src) {
    unsigned s = (unsigned)__cvta_generic_to_shared(dst);
    asm volatile("cp.async.cg.shared.global [%0], [%1], 16;" :: "r"(s), "l"(src));
}
__device__ __forceinline__ void cp_commit() { asm volatile("cp.async.commit_group;"); }
template<int N> __device__ __forceinline__ void cp_wait() {
    asm volatile("cp.async.wait_group %0;" :: "n"(N));
}
__device__ __forceinline__ uint32_t f2tf32(float f) {
    uint32_t r;
    asm("cvt.rna.tf32.f32 %0, %1;" : "=r"(r) : "f"(f));
    return r;
}
__device__ __forceinline__ void mma8(float* c, const uint32_t* a, const uint32_t* b) {
    asm volatile(
        "mma.sync.aligned.m16n8k8.row.col.f32.tf32.tf32.f32 "
        "{%0,%1,%2,%3}, {%4,%5,%6,%7}, {%8,%9}, {%0,%1,%2,%3};"
        : "+f"(c[0]), "+f"(c[1]), "+f"(c[2]), "+f"(c[3])
        : "r"(a[0]), "r"(a[1]), "r"(a[2]), "r"(a[3]), "r"(b[0]), "r"(b[1]));
}

__global__ __launch_bounds__(NTH, 4) void aux2_mma_kernel(
    const float* __restrict__ embs,
    const float* __restrict__ W_status,
    const float* __restrict__ b_status,
    const float* __restrict__ W_flight,
    const float* __restrict__ b_flight,
    float* __restrict__ out,
    int ntok)
{
    __shared__ float sA[2][BM * ASTR];   // 36,864 B
    __shared__ float sB[2][40 * BSTR];   // 11,520 B  (total 48,384 <= 48KB static)

    const int tid  = threadIdx.x;
    const int wid  = tid >> 5;
    const int lane = tid & 31;
    const int g    = lane >> 2;     // group id 0..7
    const int t    = lane & 3;      // thread-in-group 0..3
    const int m0   = wid * 32;      // warp's token base in CTA
    const long tok0 = (long)blockIdx.x * BM;
    const float* Ablk = embs + tok0 * EMB;

    // zero B pad rows 35..39 (both stages) once; never rewritten by cp.async
    for (int idx = tid; idx < 2 * 5 * BSTR; idx += NTH) {
        int st = idx / (5 * BSTR), rem = idx % (5 * BSTR);
        sB[st][(NL + rem / BSTR) * BSTR + (rem % BSTR)] = 0.0f;
    }

    auto copyA = [&](int buf, int c) {
#pragma unroll
        for (int it = 0; it < 8; ++it) {
            int idx = it * NTH + tid;          // 0..1023 : 128 rows x 8 f4-units
            int row = idx >> 3, u = idx & 7;
            cp16(&sA[buf][row * ASTR + u * 4],
                 Ablk + (long)row * EMB + c * BK + u * 4);
        }
    };
    auto copyB = [&](int buf, int c) {
#pragma unroll
        for (int it = 0; it < 3; ++it) {
            int idx = it * NTH + tid;          // need 0..279 : 35 rows x 8 units
            if (idx < NL * 8) {
                int row = idx >> 3, u = idx & 7;
                const float* src = (row < NS) ? (W_status + row * EMB)
                                              : (W_flight + (row - NS) * EMB);
                cp16(&sB[buf][row * BSTR + u * 4], src + c * BK + u * 4);
            }
        }
    };

    float acc[2][5][4];
#pragma unroll
    for (int mt = 0; mt < 2; ++mt)
#pragma unroll
        for (int nt = 0; nt < 5; ++nt)
#pragma unroll
            for (int i = 0; i < 4; ++i) acc[mt][nt][i] = 0.0f;

    // prologue
    copyA(0, 0);
    copyB(0, 0);
    cp_commit();

#pragma unroll 1
    for (int c = 0; c < NCHUNK; ++c) {
        const int buf = c & 1;
        if (c < NCHUNK - 1) {
            copyA(buf ^ 1, c + 1);
            copyB(buf ^ 1, c + 1);
            cp_commit();
            cp_wait<1>();
        } else {
            cp_wait<0>();
        }
        __syncthreads();

        const float* A = sA[buf];
        const float* B = sB[buf];
#pragma unroll
        for (int ks = 0; ks < 4; ++ks) {
            const int k0 = 8 * ks + t;
            uint32_t af[2][4];
#pragma unroll
            for (int mt = 0; mt < 2; ++mt) {
                const float* Ar = A + (m0 + mt * 16 + g) * ASTR;
                af[mt][0] = f2tf32(Ar[k0]);
                af[mt][1] = f2tf32(Ar[8 * ASTR + k0]);
                af[mt][2] = f2tf32(Ar[k0 + 4]);
                af[mt][3] = f2tf32(Ar[8 * ASTR + k0 + 4]);
            }
            uint32_t bf[5][2];
#pragma unroll
            for (int nt = 0; nt < 5; ++nt) {
                const float* Br = B + (nt * 8 + g) * BSTR;
                bf[nt][0] = f2tf32(Br[k0]);
                bf[nt][1] = f2tf32(Br[k0 + 4]);
            }
#pragma unroll
            for (int mt = 0; mt < 2; ++mt)
#pragma unroll
                for (int nt = 0; nt < 5; ++nt)
                    mma8(acc[mt][nt], af[mt], bf[nt]);
        }
        __syncthreads();   // buffer 'buf' free for refill next iter
    }

    // ---- epilogue: fragments -> logits smem (alias over sA) ----
    float* Ls = &sA[0][0];   // 128 x LSTR = 20,992 B < sA's 36,864 B
#pragma unroll
    for (int mt = 0; mt < 2; ++mt)
#pragma unroll
        for (int nt = 0; nt < 5; ++nt) {
            int r0 = m0 + mt * 16 + g;
            int cc = nt * 8 + t * 2;
            if (cc < NL) {
                Ls[r0 * LSTR + cc]       = acc[mt][nt][0];
                Ls[(r0 + 8) * LSTR + cc] = acc[mt][nt][2];
            }
            if (cc + 1 < NL) {
                Ls[r0 * LSTR + cc + 1]       = acc[mt][nt][1];
                Ls[(r0 + 8) * LSTR + cc + 1] = acc[mt][nt][3];
            }
        }
    __syncthreads();

    // ---- per-thread dual softmax + direct store (thread tid = token) ----
    {
        float sl[NS], fl[NF];
#pragma unroll
        for (int n = 0; n < NS; ++n) sl[n] = Ls[tid * LSTR + n] + b_status[n];
#pragma unroll
        for (int n = 0; n < NF; ++n) fl[n] = Ls[tid * LSTR + NS + n] + b_flight[n];

        float smax = sl[0];
#pragma unroll
        for (int n = 1; n < NS; ++n) smax = fmaxf(smax, sl[n]);
        float ssum = 0.f;
#pragma unroll
        for (int n = 0; n < NS; ++n) { sl[n] = __expf(sl[n] - smax); ssum += sl[n]; }
        float sinv = 1.f / ssum;
#pragma unroll
        for (int n = 0; n < NS; ++n) sl[n] *= sinv;

        float fm = fl[0];
#pragma unroll
        for (int n = 1; n < NF; ++n) fm = fmaxf(fm, fl[n]);
        float fsum = 0.f;
#pragma unroll
        for (int n = 0; n < NF; ++n) { fl[n] = __expf(fl[n] - fm); fsum += fl[n]; }
        float finv = 1.f / fsum;
#pragma unroll
        for (int n = 0; n < NF; ++n) fl[n] *= finv;

        const float book = sl[4], change = sl[3];
        long token = tok0 + tid;
        if (token < ntok) {
            float* op = out + token * (long)OUTC;
            op[0] = sl[0];
            op[1] = sl[2];
            op[2] = sl[1];
#pragma unroll
            for (int j = 0; j < NF; ++j) {
                op[3 + j]  = book   * fl[j];
                op[33 + j] = change * fl[j];
            }
        }
    }
}

extern "C" void kernel_launch(void* const* d_in, const int* in_sizes, int n_in,
                              void* d_out, int out_size) {
    const float* embs     = (const float*)d_in[0];
    const float* W_status = (const float*)d_in[1];
    const float* b_status = (const float*)d_in[2];
    const float* W_flight = (const float*)d_in[3];
    const float* b_flight = (const float*)d_in[4];
    float* out = (float*)d_out;

    int ntok = in_sizes[0] / EMB;   // 65536
    int blocks = ntok / BM;         // 512
    aux2_mma_kernel<<<blocks, NTH>>>(embs, W_status, b_status,
                                     W_flight, b_flight, out, ntok);
}

// round 5
// speedup vs baseline: 4.5820x; 1.0464x over previous
#include <cuda_runtime.h>
#include <cstdint>

// Skinny GEMM via mma.sync tf32 + fused dual softmax.
// C[65536,40] = embs[65536,1024] @ W^T, W = [W_status(5); W_flight(30); zeros(5)]
// BM=128 x BK=32 per chunk, cp.async double-buffered, 4 CTAs/SM.
// Key tricks vs prev round:
//  - raw fp32 bits fed as tf32 (RZ truncation), bias cancelled in epilogue
//    by multiplying dots with (1 + 2^-11*ln2*2) = 1.000677
//  - K-slot permutation {t,t+4}<->cols{2t,2t+1} makes every fragment load an
//    LDS.64; row stride 40 floats -> conflict-free (8g+2t even perm mod 32)

#define EMB    1024
#define NS     5
#define NF     30
#define NL     35
#define OUTC   63
#define BM     128
#define BK     32
#define STR    40     // floats per smem row (A and B)
#define LSTR   41
#define NTH    128
#define NCHUNK 32

#define SA_STAGE (BM * STR)          // 5120 floats
#define SB_STAGE (40 * STR)          // 1600 floats
#define SMEM_FLOATS (2 * SA_STAGE + 2 * SB_STAGE)   // 13440 -> 53760 B

__device__ __forceinline__ void cp16(float* dst, const float* src) {
    unsigned s = (unsigned)__cvta_generic_to_shared(dst);
    asm volatile("cp.async.cg.shared.global [%0], [%1], 16;" :: "r"(s), "l"(src));
}
__device__ __forceinline__ void cp_commit() { asm volatile("cp.async.commit_group;"); }
template<int N> __device__ __forceinline__ void cp_wait() {
    asm volatile("cp.async.wait_group %0;" :: "n"(N));
}
__device__ __forceinline__ void mma8(float* c, const uint32_t* a, const uint32_t* b) {
    asm volatile(
        "mma.sync.aligned.m16n8k8.row.col.f32.tf32.tf32.f32 "
        "{%0,%1,%2,%3}, {%4,%5,%6,%7}, {%8,%9}, {%0,%1,%2,%3};"
        : "+f"(c[0]), "+f"(c[1]), "+f"(c[2]), "+f"(c[3])
        : "r"(a[0]), "r"(a[1]), "r"(a[2]), "r"(a[3]), "r"(b[0]), "r"(b[1]));
}

extern __shared__ float smem[];

__global__ __launch_bounds__(NTH, 4) void aux2_mma_kernel(
    const float* __restrict__ embs,
    const float* __restrict__ W_status,
    const float* __restrict__ b_status,
    const float* __restrict__ W_flight,
    const float* __restrict__ b_flight,
    float* __restrict__ out,
    int ntok)
{
    float* sA[2] = { smem, smem + SA_STAGE };
    float* sB[2] = { smem + 2 * SA_STAGE, smem + 2 * SA_STAGE + SB_STAGE };

    const int tid  = threadIdx.x;
    const int wid  = tid >> 5;
    const int lane = tid & 31;
    const int g    = lane >> 2;     // 0..7
    const int t    = lane & 3;      // 0..3
    const int m0   = wid * 32;
    const long tok0 = (long)blockIdx.x * BM;
    const float* Ablk = embs + tok0 * EMB;

    // zero B pad rows 35..39 in both stages (cp.async never writes them)
    for (int idx = tid; idx < 2 * 5 * STR; idx += NTH) {
        int st = idx / (5 * STR), rem = idx % (5 * STR);
        sB[st][(NL + rem / STR) * STR + (rem % STR)] = 0.0f;
    }

    auto copyA = [&](int buf, int c) {
#pragma unroll
        for (int it = 0; it < 8; ++it) {
            int idx = it * NTH + tid;          // 128 rows x 8 16B-units
            int row = idx >> 3, u = idx & 7;
            cp16(&sA[buf][row * STR + u * 4],
                 Ablk + (long)row * EMB + c * BK + u * 4);
        }
    };
    auto copyB = [&](int buf, int c) {
#pragma unroll
        for (int it = 0; it < 3; ++it) {
            int idx = it * NTH + tid;          // 35 rows x 8 units = 280
            if (idx < NL * 8) {
                int row = idx >> 3, u = idx & 7;
                const float* src = (row < NS) ? (W_status + row * EMB)
                                              : (W_flight + (row - NS) * EMB);
                cp16(&sB[buf][row * STR + u * 4], src + c * BK + u * 4);
            }
        }
    };

    float acc[2][5][4];
#pragma unroll
    for (int mt = 0; mt < 2; ++mt)
#pragma unroll
        for (int nt = 0; nt < 5; ++nt)
#pragma unroll
            for (int i = 0; i < 4; ++i) acc[mt][nt][i] = 0.0f;

    copyA(0, 0);
    copyB(0, 0);
    cp_commit();

#pragma unroll 1
    for (int c = 0; c < NCHUNK; ++c) {
        const int buf = c & 1;
        if (c < NCHUNK - 1) {
            copyA(buf ^ 1, c + 1);
            copyB(buf ^ 1, c + 1);
            cp_commit();
            cp_wait<1>();
        } else {
            cp_wait<0>();
        }
        __syncthreads();

        const float* A = sA[buf];
        const float* B = sB[buf];
#pragma unroll
        for (int ks = 0; ks < 4; ++ks) {
            const int cof = 8 * ks + 2 * t;     // physical col pair for this thread
            // A fragments: rows (m0+mt*16+g) and (+8); cols (cof, cof+1)
            uint32_t af[2][4];
#pragma unroll
            for (int mt = 0; mt < 2; ++mt) {
                uint2 v0 = *(const uint2*)(A + (m0 + mt * 16 + g) * STR + cof);
                uint2 v1 = *(const uint2*)(A + (m0 + mt * 16 + g + 8) * STR + cof);
                af[mt][0] = v0.x; af[mt][2] = v0.y;   // k-slot t, t+4
                af[mt][1] = v1.x; af[mt][3] = v1.y;
            }
            uint32_t bf[5][2];
#pragma unroll
            for (int nt = 0; nt < 5; ++nt) {
                uint2 v = *(const uint2*)(B + (nt * 8 + g) * STR + cof);
                bf[nt][0] = v.x; bf[nt][1] = v.y;
            }
#pragma unroll
            for (int mt = 0; mt < 2; ++mt)
#pragma unroll
                for (int nt = 0; nt < 5; ++nt)
                    mma8(acc[mt][nt], af[mt], bf[nt]);
        }
        __syncthreads();
    }

    // ---- epilogue: fragments -> logits smem (alias over sA) ----
    float* Ls = smem;   // 128 x 41 floats = 20,992 B, fits in stage area
#pragma unroll
    for (int mt = 0; mt < 2; ++mt)
#pragma unroll
        for (int nt = 0; nt < 5; ++nt) {
            int r0 = m0 + mt * 16 + g;
            int cc = nt * 8 + t * 2;
            if (cc < NL) {
                Ls[r0 * LSTR + cc]       = acc[mt][nt][0];
                Ls[(r0 + 8) * LSTR + cc] = acc[mt][nt][2];
            }
            if (cc + 1 < NL) {
                Ls[r0 * LSTR + cc + 1]       = acc[mt][nt][1];
                Ls[(r0 + 8) * LSTR + cc + 1] = acc[mt][nt][3];
            }
        }
    __syncthreads();

    // ---- per-thread dual softmax + store; RZ-bias correction on dots ----
    {
        const float corr = 1.000677f;   // 1 + 2 * 2^-11 * ln2 (tf32 RZ bias)
        float sl[NS], fl[NF];
#pragma unroll
        for (int n = 0; n < NS; ++n) sl[n] = Ls[tid * LSTR + n] * corr + b_status[n];
#pragma unroll
        for (int n = 0; n < NF; ++n) fl[n] = Ls[tid * LSTR + NS + n] * corr + b_flight[n];

        float smax = sl[0];
#pragma unroll
        for (int n = 1; n < NS; ++n) smax = fmaxf(smax, sl[n]);
        float ssum = 0.f;
#pragma unroll
        for (int n = 0; n < NS; ++n) { sl[n] = __expf(sl[n] - smax); ssum += sl[n]; }
        float sinv = 1.f / ssum;
#pragma unroll
        for (int n = 0; n < NS; ++n) sl[n] *= sinv;

        float fm = fl[0];
#pragma unroll
        for (int n = 1; n < NF; ++n) fm = fmaxf(fm, fl[n]);
        float fsum = 0.f;
#pragma unroll
        for (int n = 0; n < NF; ++n) { fl[n] = __expf(fl[n] - fm); fsum += fl[n]; }
        float finv = 1.f / fsum;
#pragma unroll
        for (int n = 0; n < NF; ++n) fl[n] *= finv;

        const float book = sl[4], change = sl[3];
        long token = tok0 + tid;
        if (token < ntok) {
            float* op = out + token * (long)OUTC;
            op[0] = sl[0];
            op[1] = sl[2];
            op[2] = sl[1];
#pragma unroll
            for (int j = 0; j < NF; ++j) {
                op[3 + j]  = book   * fl[j];
                op[33 + j] = change * fl[j];
            }
        }
    }
}

extern "C" void kernel_launch(void* const* d_in, const int* in_sizes, int n_in,
                              void* d_out, int out_size) {
    const float* embs     = (const float*)d_in[0];
    const float* W_status = (const float*)d_in[1];
    const float* b_status = (const float*)d_in[2];
    const float* W_flight = (const float*)d_in[3];
    const float* b_flight = (const float*)d_in[4];
    float* out = (float*)d_out;

    static int configured = 0;
    if (!configured) {
        cudaFuncSetAttribute(aux2_mma_kernel,
                             cudaFuncAttributeMaxDynamicSharedMemorySize,
                             SMEM_FLOATS * 4);
        configured = 1;
    }

    int ntok = in_sizes[0] / EMB;   // 65536
    int blocks = ntok / BM;         // 512
    aux2_mma_kernel<<<blocks, NTH, SMEM_FLOATS * 4>>>(
        embs, W_status, b_status, W_flight, b_flight, out, ntok);
}